// round 6
// baseline (speedup 1.0000x reference)
#include <cuda_runtime.h>
#include <cuda_fp16.h>

// HausdorffDTLoss, [4,1,256,256] fp32 inputs.
// loss = mean( (pred-target)^2 * (pred_dt^2 + target_dt^2) )
// dt^2 = min(F_fg,BIG) + min(F_~fg,BIG)  (exactly one EDT is 0 per pixel).
// F = separable 1D min-plus squared-distance transform (y-pass then x-pass),
// windowed outward scan with per-lane early exit (bit-exact: all candidates
// are f[j]+(i-j)^2 with f>=0; d^2>=min can't win; clamped-index candidates
// are dominated by the d=|i-j| candidate already evaluated).
//
// Byte-diet: vertical pass packs both masks into ONE signed fp16 per pixel
// (v = mF - mN; one of them is always exactly 0; +/-inf = BIG sentinel), and
// e=(p-t)^2 is precomputed as uint16 fixed-point, so stage2 reads ~2MB
// instead of ~6MB.

#define BIGF 1e10f
#define HW 256
#define IMG 65536
#define TOTAL 262144
#define ARR 257

// [img(2)][b(4)][x][y] signed vertical-pass field (y fast; transposed)
__device__ __align__(16) __half g_V[2 * 4 * IMG];
// [b(4)][y][x] quantized squared error, e_q = round(e * 65535)
__device__ __align__(16) unsigned short g_E[4 * IMG];
__device__ int g_fgany[8];          // [img*4 + b]; zero-init, self-reset
__device__ double g_accum;          // zero-init, self-reset
__device__ unsigned int g_counter;  // zero-init, self-reset

// Windowed min-plus over 4 signed arrays (stride ARR) concurrently.
// Signed decode: fg-field value = max(v,0), ~fg-field value = max(-v,0).
__device__ __forceinline__ void scan4s(const float* __restrict__ A, int i,
                                       float mF[4], float mN[4])
{
    #pragma unroll
    for (int j = 0; j < 4; ++j) {
        float f = A[i + j * ARR];
        mF[j] = fmaxf(f, 0.0f);
        mN[j] = fmaxf(-f, 0.0f);
    }
    float d2 = 1.0f, st = 3.0f;      // d2 = d*d, st = 2d+1 (exact in fp32)
    #pragma unroll 1
    for (int d = 1; d < 256; ++d) {
        float mx = fmaxf(fmaxf(fmaxf(mF[0], mN[0]), fmaxf(mF[1], mN[1])),
                         fmaxf(fmaxf(mF[2], mN[2]), fmaxf(mF[3], mN[3])));
        if (d2 >= mx) break;         // no farther candidate can win any min
        int il = i - d; il = il < 0 ? 0 : il;       // clamped: dominated cands
        int ir = i + d; ir = ir > 255 ? 255 : ir;
        #pragma unroll
        for (int j = 0; j < 4; ++j) {
            float vl = A[il + j * ARR];
            float vr = A[ir + j * ARR];
            mF[j] = fminf(mF[j], fminf(fmaxf(vl, 0.0f), fmaxf(vr, 0.0f)) + d2);
            mN[j] = fminf(mN[j], fminf(fmaxf(-vl, 0.0f), fmaxf(-vr, 0.0f)) + d2);
        }
        d2 += st; st += 2.0f;
    }
}

// ---------------------------------------------------------------------------
// Stage 1: vertical pass. Block = (b, 4-column tile), BOTH images.
// 256 blocks x 512 threads. Thread (img = tid>>8, y = tid&255) loads one
// float4 (4 cols) of its image. Computes e (uint16), fg_any, then scans
// 4 signed arrays (cols 2q,2q+1 x 2 images) and writes packed fp16 V.
// ---------------------------------------------------------------------------
__global__ __launch_bounds__(512, 2) void stage1_kernel(
    const float* __restrict__ pred, const float* __restrict__ target)
{
    __shared__ float s[8 * ARR];     // 8 signed arrays (4 cols x 2 imgs)

    int bid = blockIdx.x;            // 0..255
    int xt  = bid & 63;
    int b   = bid >> 6;
    int x0  = xt * 4;
    int tid = threadIdx.x;
    int img = tid >> 8;              // 0 = pred, 1 = target (warp-uniform)
    int y   = tid & 255;

    const float* im = (img ? target : pred) + b * IMG + y * HW + x0;
    float4 v = *reinterpret_cast<const float4*>(im);     // coalesced 16B

    // Stash raw values: array a = col*2 + img
    s[(0 * 2 + img) * ARR + y] = v.x;
    s[(1 * 2 + img) * ARR + y] = v.y;
    s[(2 * 2 + img) * ARR + y] = v.z;
    s[(3 * 2 + img) * ARR + y] = v.w;

    bool fgl = (v.x > 0.5f) || (v.y > 0.5f) || (v.z > 0.5f) || (v.w > 0.5f);
    if (__any_sync(0xFFFFFFFFu, fgl) && (tid & 31) == 0)
        atomicOr(&g_fgany[img * 4 + b], 1);
    __syncthreads();

    // pred-threads compute e against stashed target values.
    if (img == 0) {
        float d0 = v.x - s[1 * ARR + y];
        float d1 = v.y - s[3 * ARR + y];
        float d2_ = v.z - s[5 * ARR + y];
        float d3 = v.w - s[7 * ARR + y];
        ushort4 eq;
        eq.x = (unsigned short)(d0 * d0 * 65535.0f + 0.5f);
        eq.y = (unsigned short)(d1 * d1 * 65535.0f + 0.5f);
        eq.z = (unsigned short)(d2_ * d2_ * 65535.0f + 0.5f);
        eq.w = (unsigned short)(d3 * d3 * 65535.0f + 0.5f);
        *reinterpret_cast<ushort4*>(g_E + b * IMG + y * HW + x0) = eq;
    }
    __syncthreads();                 // raw values consumed

    // Convert own slots in place to signed masks (+BIG fg / -BIG bg).
    s[(0 * 2 + img) * ARR + y] = (v.x > 0.5f) ? BIGF : -BIGF;
    s[(1 * 2 + img) * ARR + y] = (v.y > 0.5f) ? BIGF : -BIGF;
    s[(2 * 2 + img) * ARR + y] = (v.z > 0.5f) ? BIGF : -BIGF;
    s[(3 * 2 + img) * ARR + y] = (v.w > 0.5f) ? BIGF : -BIGF;
    __syncthreads();

    // Thread group q = tid>>8 scans arrays 4q..4q+3 at site i = tid&255.
    int q = img;
    int i = y;
    float mF[4], mN[4];
    scan4s(s + (4 * q) * ARR, i, mF, mN);

    // Pack: V = mF - mN (one is exactly 0); BIG -> +/-inf in fp16.
    #pragma unroll
    for (int j = 0; j < 4; ++j) {
        int a = 4 * q + j;
        int u = a >> 1, m = a & 1;   // column u, image m
        g_V[(m * 4 + b) * IMG + (x0 + u) * HW + i] = __float2half(mF[j] - mN[j]);
    }
}

// ---------------------------------------------------------------------------
// Stage 2: horizontal pass + loss + reduction + finalize.
// Block = (img, b, 8-row tile). 256 blocks x 512 threads.
// Reads only g_V (1MB) and g_E (1MB across both image halves).
// ---------------------------------------------------------------------------
__global__ __launch_bounds__(512, 2) void stage2_kernel(float* __restrict__ out)
{
    __shared__ float s[8 * ARR];     // 8 signed row arrays

    int bid = blockIdx.x;            // 0..255
    int yt  = bid & 31;
    int b   = (bid >> 5) & 3;
    int in  = bid >> 7;
    int y0  = yt * 8;
    int tid = threadIdx.x;

    const __half* V = g_V + (in * 4 + b) * IMG;   // [x][y] layout
    #pragma unroll
    for (int it = 0; it < 4; ++it) {
        int idx = it * 512 + tid;
        int x = idx >> 3;            // x
        int r = idx & 7;             // row within tile
        s[r * ARR + x] = __half2float(V[x * HW + y0 + r]);  // 16B chunks
    }
    __syncthreads();

    // Thread group q = tid>>8 scans rows 4q..4q+3 at site x = tid&255.
    int q = tid >> 8;
    int x = tid & 255;
    float mF[4], mN[4];
    scan4s(s + (4 * q) * ARR, x, mF, mN);

    int fg = g_fgany[in * 4 + b];
    double acc = 0.0;
    #pragma unroll
    for (int j = 0; j < 4; ++j) {
        float dv = fminf(mF[j], BIGF) + fminf(mN[j], BIGF);  // dt^2
        unsigned short eq = g_E[b * IMG + (y0 + 4 * q + j) * HW + x];
        float e = (float)eq * (1.0f / 65535.0f);
        acc += (double)e * (double)dv;
    }
    if (!fg) acc = 0.0;              // empty-foreground image contributes 0

    // Warp reduce, then 16 warp sums via reused smem.
    #pragma unroll
    for (int o = 16; o > 0; o >>= 1)
        acc += __shfl_down_sync(0xFFFFFFFFu, acc, o);

    __syncthreads();                 // done reading s
    double* ws = (double*)s;
    int wid = tid >> 5, lane = tid & 31;
    if (lane == 0) ws[wid] = acc;
    __syncthreads();

    if (wid == 0 && lane == 0) {
        double bsum = 0.0;
        #pragma unroll
        for (int w = 0; w < 16; ++w) bsum += ws[w];
        atomicAdd(&g_accum, bsum);
        __threadfence();
        unsigned done = atomicAdd(&g_counter, 1u);
        if (done == gridDim.x - 1) {
            double tot = atomicAdd(&g_accum, 0.0);     // coherent read
            out[0] = (float)(tot * (1.0 / (double)TOTAL));
            // Self-reset device state for the next graph replay.
            g_accum = 0.0;
            g_counter = 0u;
            #pragma unroll
            for (int i2 = 0; i2 < 8; ++i2) g_fgany[i2] = 0;
        }
    }
}

extern "C" void kernel_launch(void* const* d_in, const int* in_sizes, int n_in,
                              void* d_out, int out_size) {
    const float* pred   = (const float*)d_in[0];
    const float* target = (const float*)d_in[1];
    float* out = (float*)d_out;

    stage1_kernel<<<256, 512>>>(pred, target);
    stage2_kernel<<<256, 512>>>(out);
}

// round 7
// speedup vs baseline: 1.0135x; 1.0135x over previous
#include <cuda_runtime.h>
#include <cuda_fp16.h>

// HausdorffDTLoss, [4,1,256,256] fp32 inputs. Single fused kernel.
// loss = mean( (pred-target)^2 * (pred_dt^2 + target_dt^2) )
// dt^2 = min(F_fg,BIG) + min(F_~fg,BIG)  (exactly one EDT is 0 per pixel).
// F = separable 1D min-plus squared-distance transform (y-pass then x-pass),
// windowed outward scan with per-lane early exit (exact: all candidates are
// f[j]+(i-j)^2 with f>=0; d^2>=min can't win; clamped-index candidates are
// dominated by the already-evaluated d=|i-j| candidate).
//
// Phase 1 (per block: one (b, 4-col) tile, both images): vertical pass,
// packs both masks into ONE signed fp16 (v = mF - mN; one is always 0),
// precomputes e=(p-t)^2 as uint16. Software grid barrier (all 256 blocks
// co-resident: 512 thr x 2 blocks/SM x 148 SMs = 296 slots). Phase 2
// (per block: one (img, b, 8-row) tile): horizontal pass + loss reduction.

#define BIGF 1e10f
#define HW 256
#define IMG 65536
#define TOTAL 262144
#define ARR 257
#define NBLK 256

// [img(2)][b(4)][x][y] signed vertical-pass field (y fast; transposed)
__device__ __align__(16) __half g_V[2 * 4 * IMG];
// [b(4)][y][x] quantized squared error, e_q = round(e * 65535)
__device__ __align__(16) unsigned short g_E[4 * IMG];
__device__ int g_fgany[8];          // [img*4 + b]; zero-init, self-reset
__device__ double g_accum;          // zero-init, self-reset
__device__ unsigned int g_counter;  // zero-init, self-reset
__device__ volatile unsigned int g_bar;  // zero-init, self-reset

// Windowed min-plus over 4 signed arrays (stride ARR) concurrently.
// Signed decode: fg-field value = max(v,0), ~fg-field value = max(-v,0).
__device__ __forceinline__ void scan4s(const float* __restrict__ A, int i,
                                       float mF[4], float mN[4])
{
    #pragma unroll
    for (int j = 0; j < 4; ++j) {
        float f = A[i + j * ARR];
        mF[j] = fmaxf(f, 0.0f);
        mN[j] = fmaxf(-f, 0.0f);
    }
    float d2 = 1.0f, st = 3.0f;      // d2 = d*d, st = 2d+1 (exact in fp32)
    #pragma unroll 1
    for (int d = 1; d < 256; ++d) {
        float mx = fmaxf(fmaxf(fmaxf(mF[0], mN[0]), fmaxf(mF[1], mN[1])),
                         fmaxf(fmaxf(mF[2], mN[2]), fmaxf(mF[3], mN[3])));
        if (d2 >= mx) break;         // no farther candidate can win any min
        int il = i - d; il = il < 0 ? 0 : il;       // clamped: dominated
        int ir = i + d; ir = ir > 255 ? 255 : ir;
        #pragma unroll
        for (int j = 0; j < 4; ++j) {
            float vl = A[il + j * ARR];
            float vr = A[ir + j * ARR];
            mF[j] = fminf(mF[j], fminf(fmaxf(vl, 0.0f), fmaxf(vr, 0.0f)) + d2);
            mN[j] = fminf(mN[j], fminf(fmaxf(-vl, 0.0f), fmaxf(-vr, 0.0f)) + d2);
        }
        d2 += st; st += 2.0f;
    }
}

__global__ __launch_bounds__(512, 2) void fused_kernel(
    const float* __restrict__ pred, const float* __restrict__ target,
    float* __restrict__ out)
{
    __shared__ float s[8 * ARR];     // reused across both phases
    int bid = blockIdx.x;            // 0..255
    int tid = threadIdx.x;

    // ===================== Phase 1: vertical pass ========================
    {
        int xt  = bid & 63;
        int b   = bid >> 6;
        int x0  = xt * 4;
        int img = tid >> 8;          // 0 = pred, 1 = target (warp-uniform)
        int y   = tid & 255;

        const float* im = (img ? target : pred) + b * IMG + y * HW + x0;
        float4 v = *reinterpret_cast<const float4*>(im);   // coalesced 16B

        // Stash raw values: array a = col*2 + img
        s[(0 * 2 + img) * ARR + y] = v.x;
        s[(1 * 2 + img) * ARR + y] = v.y;
        s[(2 * 2 + img) * ARR + y] = v.z;
        s[(3 * 2 + img) * ARR + y] = v.w;

        bool fgl = (v.x > 0.5f) || (v.y > 0.5f) || (v.z > 0.5f) || (v.w > 0.5f);
        if (__any_sync(0xFFFFFFFFu, fgl) && (tid & 31) == 0)
            atomicOr(&g_fgany[img * 4 + b], 1);
        __syncthreads();

        // pred-threads compute e against stashed target values.
        if (img == 0) {
            float d0 = v.x - s[1 * ARR + y];
            float d1 = v.y - s[3 * ARR + y];
            float d2_ = v.z - s[5 * ARR + y];
            float d3 = v.w - s[7 * ARR + y];
            ushort4 eq;
            eq.x = (unsigned short)(d0 * d0 * 65535.0f + 0.5f);
            eq.y = (unsigned short)(d1 * d1 * 65535.0f + 0.5f);
            eq.z = (unsigned short)(d2_ * d2_ * 65535.0f + 0.5f);
            eq.w = (unsigned short)(d3 * d3 * 65535.0f + 0.5f);
            *reinterpret_cast<ushort4*>(g_E + b * IMG + y * HW + x0) = eq;
        }
        __syncthreads();             // raw values consumed

        // Convert own slots in place to signed masks (+BIG fg / -BIG bg).
        s[(0 * 2 + img) * ARR + y] = (v.x > 0.5f) ? BIGF : -BIGF;
        s[(1 * 2 + img) * ARR + y] = (v.y > 0.5f) ? BIGF : -BIGF;
        s[(2 * 2 + img) * ARR + y] = (v.z > 0.5f) ? BIGF : -BIGF;
        s[(3 * 2 + img) * ARR + y] = (v.w > 0.5f) ? BIGF : -BIGF;
        __syncthreads();

        // Thread group q = img scans arrays 4q..4q+3 at site y.
        float mF[4], mN[4];
        scan4s(s + (4 * img) * ARR, y, mF, mN);

        // Pack: V = mF - mN (one is exactly 0); BIG -> +/-inf in fp16.
        #pragma unroll
        for (int j = 0; j < 4; ++j) {
            int a = 4 * img + j;
            int u = a >> 1, m = a & 1;   // column u, image m
            g_V[(m * 4 + b) * IMG + (x0 + u) * HW + y] =
                __float2half(mF[j] - mN[j]);
        }
    }

    // ===================== Grid barrier ==================================
    __threadfence();                 // publish g_V / g_E / g_fgany
    __syncthreads();
    if (tid == 0) {
        atomicAdd((unsigned int*)&g_bar, 1u);
        while (g_bar < NBLK) __nanosleep(32);
    }
    __syncthreads();
    __threadfence();                 // acquire other blocks' writes

    // ===================== Phase 2: horizontal pass + loss ===============
    {
        int yt  = bid & 31;
        int b   = (bid >> 5) & 3;
        int in  = bid >> 7;
        int y0  = yt * 8;

        const __half* V = g_V + (in * 4 + b) * IMG;   // [x][y] layout
        #pragma unroll
        for (int it = 0; it < 4; ++it) {
            int idx = it * 512 + tid;
            int x = idx >> 3;        // x
            int r = idx & 7;         // row within tile
            s[r * ARR + x] = __half2float(V[x * HW + y0 + r]);
        }
        __syncthreads();

        int q = tid >> 8;            // rows 4q..4q+3
        int x = tid & 255;
        float mF[4], mN[4];
        scan4s(s + (4 * q) * ARR, x, mF, mN);

        int fg = g_fgany[in * 4 + b];
        double acc = 0.0;
        #pragma unroll
        for (int j = 0; j < 4; ++j) {
            float dv = fminf(mF[j], BIGF) + fminf(mN[j], BIGF);  // dt^2
            unsigned short eq = g_E[b * IMG + (y0 + 4 * q + j) * HW + x];
            float e = (float)eq * (1.0f / 65535.0f);
            acc += (double)e * (double)dv;
        }
        if (!fg) acc = 0.0;          // empty-foreground image contributes 0

        // Warp reduce, then 16 warp sums via reused smem.
        #pragma unroll
        for (int o = 16; o > 0; o >>= 1)
            acc += __shfl_down_sync(0xFFFFFFFFu, acc, o);

        __syncthreads();             // done reading s
        double* ws = (double*)s;
        int wid = tid >> 5, lane = tid & 31;
        if (lane == 0) ws[wid] = acc;
        __syncthreads();

        if (wid == 0 && lane == 0) {
            double bsum = 0.0;
            #pragma unroll
            for (int w = 0; w < 16; ++w) bsum += ws[w];
            atomicAdd(&g_accum, bsum);
            __threadfence();
            unsigned done = atomicAdd(&g_counter, 1u);
            if (done == NBLK - 1) {
                double tot = atomicAdd(&g_accum, 0.0);     // coherent read
                out[0] = (float)(tot * (1.0 / (double)TOTAL));
                // Self-reset device state for the next graph replay.
                g_accum = 0.0;
                g_counter = 0u;
                g_bar = 0u;
                #pragma unroll
                for (int i2 = 0; i2 < 8; ++i2) g_fgany[i2] = 0;
            }
        }
    }
}

extern "C" void kernel_launch(void* const* d_in, const int* in_sizes, int n_in,
                              void* d_out, int out_size) {
    const float* pred   = (const float*)d_in[0];
    const float* target = (const float*)d_in[1];
    float* out = (float*)d_out;

    fused_kernel<<<NBLK, 512>>>(pred, target, out);
}